// round 9
// baseline (speedup 1.0000x reference)
#include <cuda_runtime.h>
#include <cuda_bf16.h>
#include <cstdint>

// InteractionArch via base-ISA tensor cores (mma.sync bf16 x3 emulated fp32).
//
// WARP-AUTONOMOUS version: each warp owns one batch end-to-end (load,
// convert, MMA, stage, writeout) touching only its private 4 KB smem region,
// so there are NO __syncthreads at all -- only __syncwarp. Round 8 showed
// 50% reg-limited occupancy with issue=42%: the CTA barriers made all 4
// warps wait for the slowest LDG each stage. Decoupling the warps lets
// resident warps cover each other's memory latency.
//
//   D = H*H^T + H*L^T + L*H^T   (fp32 = bf16 hi + lo; L*L^T ~ 2^-16, dropped)
// upper tiles T00/T01/T11 only; 18 HMMA m16n8k16 per k16-step.
//
// K in 4 stages of 32 (one 128 B line per feature row per stage -> fully
// sector-efficient LDG). smem 16 KB/CTA; regs ~64 -> 8 CTAs/SM.
//
// Swizzle (64 B bf16 rows, 4 x 16 B chunks): chunk c of row r at position
// c ^ ((r>>1)&3); every octet phase of STS.128 / ldmatrix hits 8 distinct
// 16 B bank groups (verified {0,4,1,5,2,6,3,7}).

#define FEAT 27
#define KDIM 128
#define NPAIR 351
#define GROUP 4
#define THREADS 128
#define LO_OFF 8192            // byte offset of lo region
#define BATCH_BYTES 2048       // 32 rows x 64 B (bf16)
#define STG_STRIDE 28          // staging row stride (floats)

__device__ __forceinline__ void split2(float x, float y, uint32_t& h, uint32_t& l) {
    asm("cvt.rn.satfinite.bf16x2.f32 %0, %1, %2;" : "=r"(h) : "f"(y), "f"(x));
    float hx = __uint_as_float(h << 16);
    float hy = __uint_as_float(h & 0xffff0000u);
    float lx = x - hx, ly = y - hy;
    asm("cvt.rn.satfinite.bf16x2.f32 %0, %1, %2;" : "=r"(l) : "f"(ly), "f"(lx));
}

__device__ __forceinline__ void ldx4(uint32_t addr, uint32_t* r) {
    asm volatile("ldmatrix.sync.aligned.m8n8.x4.shared.b16 {%0,%1,%2,%3}, [%4];"
                 : "=r"(r[0]), "=r"(r[1]), "=r"(r[2]), "=r"(r[3]) : "r"(addr));
}

__device__ __forceinline__ void mma16816(float* c, const uint32_t* a, const uint32_t* b) {
    asm volatile(
        "mma.sync.aligned.m16n8k16.row.col.f32.bf16.bf16.f32 "
        "{%0,%1,%2,%3}, {%4,%5,%6,%7}, {%8,%9}, {%0,%1,%2,%3};"
        : "+f"(c[0]), "+f"(c[1]), "+f"(c[2]), "+f"(c[3])
        : "r"(a[0]), "r"(a[1]), "r"(a[2]), "r"(a[3]), "r"(b[0]), "r"(b[1]));
}

__global__ __launch_bounds__(THREADS)
void interaction_kernel(const float* __restrict__ dense,
                        const float* __restrict__ sparse,
                        float* __restrict__ out,
                        int B)
{
    __shared__ __align__(1024) char smem[16384];

    const int tid = threadIdx.x;
    const int wid = tid >> 5;
    const int lane = tid & 31;
    const long b = (long)blockIdx.x * GROUP + wid;   // this warp's batch

    uint32_t sb;
    asm("{ .reg .u64 t; cvta.to.shared.u64 t, %1; cvt.u32.u64 %0, t; }"
        : "=r"(sb) : "l"((void*)smem));

    const uint32_t hbase = sb + wid * BATCH_BYTES;   // this warp's bf16 hi buffer
    const uint32_t lbase = hbase + LO_OFF;

    // ---- per-lane source row pointer (lane = feature row) ----
    const bool valid = (lane < FEAT) && (b < B);
    const float* src = (lane == 0)
        ? dense + b * KDIM
        : sparse + ((b * 26) + (lane - 1)) * (long)KDIM;

    // ldmatrix lane selectors (same as rounds 7-8, verified correct)
    const int arow = lane & 15;
    const int asel = lane >> 4;
    const int brow = (lane & 7) + ((lane & 16) >> 1);
    const int bsel = (lane >> 3) & 1;
    const int aswz = (arow >> 1) & 3;
    const int bswz = (brow >> 1) & 3;

    // STS base for this lane's row
    const uint32_t strow = lane * 64;
    const int lswz = (lane >> 1) & 3;

    float acc[6][4] = {};   // T00a,T00b,T01a,T01b,T11a,T11b

#pragma unroll
    for (int s2 = 0; s2 < 4; ++s2) {
        // ---- Load + convert: lane loads 32 floats (one 128 B line) ----
#pragma unroll
        for (int cc = 0; cc < 4; ++cc) {
            uint4 hi = make_uint4(0u, 0u, 0u, 0u);
            uint4 lo = make_uint4(0u, 0u, 0u, 0u);
            if (valid) {
                const float* p = src + s2 * 32 + cc * 8;
                float4 a0 = *reinterpret_cast<const float4*>(p);
                float4 a1 = *reinterpret_cast<const float4*>(p + 4);
                split2(a0.x, a0.y, hi.x, lo.x);
                split2(a0.z, a0.w, hi.y, lo.y);
                split2(a1.x, a1.y, hi.z, lo.z);
                split2(a1.z, a1.w, hi.w, lo.w);
            }
            const uint32_t off = strow + ((cc ^ lswz) << 4);
            *reinterpret_cast<uint4*>((char*)smem + (hbase - sb) + off) = hi;
            *reinterpret_cast<uint4*>((char*)smem + (lbase - sb) + off) = lo;
        }
        __syncwarp();

        // ---- Compute: 2 k16-steps over this 32-wide stage ----
#pragma unroll
        for (int s = 0; s < 2; ++s) {
            const int ac = 2 * s + asel;
            const int bc = 2 * s + bsel;

            uint32_t A0h[4], A0l[4], A1h[4], A1l[4];
            uint32_t B0h[4], B0l[4], B1h[4], B1l[4];

            const uint32_t offA0 = arow * 64 + ((ac ^ aswz) << 4);
            const uint32_t offA1 = (arow + 16) * 64 + ((ac ^ aswz) << 4);
            const uint32_t offB0 = brow * 64 + ((bc ^ bswz) << 4);
            const uint32_t offB1 = (brow + 16) * 64 + ((bc ^ bswz) << 4);

            ldx4(hbase + offA0, A0h);  ldx4(lbase + offA0, A0l);
            ldx4(hbase + offA1, A1h);  ldx4(lbase + offA1, A1l);
            ldx4(hbase + offB0, B0h);  ldx4(lbase + offB0, B0l);
            ldx4(hbase + offB1, B1h);  ldx4(lbase + offB1, B1l);

            // H * H^T
            mma16816(acc[0], A0h, B0h);      mma16816(acc[1], A0h, B0h + 2);
            mma16816(acc[2], A0h, B1h);      mma16816(acc[3], A0h, B1h + 2);
            mma16816(acc[4], A1h, B1h);      mma16816(acc[5], A1h, B1h + 2);
            // H * L^T
            mma16816(acc[0], A0h, B0l);      mma16816(acc[1], A0h, B0l + 2);
            mma16816(acc[2], A0h, B1l);      mma16816(acc[3], A0h, B1l + 2);
            mma16816(acc[4], A1h, B1l);      mma16816(acc[5], A1h, B1l + 2);
            // L * H^T
            mma16816(acc[0], A0l, B0h);      mma16816(acc[1], A0l, B0h + 2);
            mma16816(acc[2], A0l, B1h);      mma16816(acc[3], A0l, B1h + 2);
            mma16816(acc[4], A1l, B1h);      mma16816(acc[5], A1l, B1h + 2);
        }
        __syncwarp();   // warp's reads done before its next-stage STS
    }

    // ---- Stage triangle into this warp's own 4 KB (rows<16 in hi, rest in lo) ----
    // addr(r) = (r < 16 ? hbase : lbase - 16*112) + r*112   (112 B = 28 floats)
    {
        float* hptr = reinterpret_cast<float*>((char*)smem + (hbase - sb));
        float* lptr = reinterpret_cast<float*>((char*)smem + (lbase - sb));
        const int r0 = lane >> 2;
        const int c0 = (lane & 3) * 2;
        const int MR[6] = {0, 0, 0, 0, 16, 16};
        const int NC[6] = {0, 8, 16, 24, 16, 24};
#pragma unroll
        for (int t = 0; t < 6; ++t) {
#pragma unroll
            for (int hrow = 0; hrow < 2; ++hrow) {
                const int rr = MR[t] + r0 + hrow * 8;
                const int cc = NC[t] + c0;
                if (rr < FEAT && cc < 28) {
                    float* base = (rr < 16) ? (hptr + rr * STG_STRIDE)
                                            : (lptr + (rr - 16) * STG_STRIDE);
                    base[cc] = acc[t][hrow * 2];
                    if (cc + 1 < 28) base[cc + 1] = acc[t][hrow * 2 + 1];
                }
            }
        }
    }
    __syncwarp();

    // ---- Per-warp coalesced writeout: 351 floats ----
    if (b < B) {
        const float* hptr = reinterpret_cast<const float*>((char*)smem + (hbase - sb));
        const float* lptr = reinterpret_cast<const float*>((char*)smem + (lbase - sb));
        float* ob = out + b * NPAIR;
#pragma unroll
        for (int k = 0; k < 11; ++k) {
            const int e = k * 32 + lane;
            if (e < NPAIR) {
                // invert strict-upper-triangle index e -> (i, j)
                int i = (int)((53.0f - sqrtf(2809.0f - 8.0f * (float)e)) * 0.5f);
                if (i < 0) i = 0;
                if (i > 25) i = 25;
#pragma unroll
                for (int q = 0; q < 2; ++q) {
                    if (i < 25 && e >= (i + 1) * (52 - i) / 2) ++i;
                    if (i > 0 && e < i * (53 - i) / 2) --i;
                }
                const int j = i + 1 + (e - i * (53 - i) / 2);
                const float* base = (i < 16) ? (hptr + i * STG_STRIDE)
                                             : (lptr + (i - 16) * STG_STRIDE);
                ob[e] = base[j];
            }
        }
    }
}

extern "C" void kernel_launch(void* const* d_in, const int* in_sizes, int n_in,
                              void* d_out, int out_size)
{
    const float* dense  = (const float*)d_in[0];   // (B, 128)
    const float* sparse = (const float*)d_in[1];   // (B, 26, 128)
    float* out = (float*)d_out;                    // (B, 351)

    const int B = in_sizes[0] / KDIM;
    const int grid = (B + GROUP - 1) / GROUP;
    interaction_kernel<<<grid, THREADS>>>(dense, sparse, out, B);
}

// round 10
// speedup vs baseline: 1.3638x; 1.3638x over previous
#include <cuda_runtime.h>
#include <cuda_bf16.h>
#include <cstdint>

// InteractionArch via base-ISA tensor cores (mma.sync bf16 x3 emulated fp32),
// SOFTWARE-PIPELINED: double-buffered bf16 smem + register prefetch of the
// next K-stage so LDG latency hides under MMA work. Round 8 layout (coalesced
// loads, swizzle, tiles) kept verbatim; round 9's per-lane-row loads caused a
// 27-wavefront/instr L1 blowup and are reverted.
//
//   D = H*H^T + H*L^T + L*H^T  (fp32 = bf16 hi + lo; L*L^T ~ 2^-16, dropped)
// upper tiles T00/T01/T11; 18 HMMA m16n8k16 per k16-step; K = 4 stages of 32.
//
// Pipeline per stage s:  split+STS buf[s&1] ; BAR ; LDG(s+1)->regs ;
//                        compute(s) from buf[s&1]
// Hazard: readers of buf[(s+1)&1] are compute(s-1), all complete before BAR_s
// (program order: compute(s-1) -> STS(s) -> BAR_s). One barrier per stage.
//
// Swizzle (64 B bf16 rows, 4 x 16 B chunks): chunk c of row r at position
// c ^ ((r>>1)&3); every octet of STS.128 / ldmatrix hits 8 distinct groups.

#define FEAT 27
#define KDIM 128
#define NPAIR 351
#define GROUP 4
#define THREADS 128
#define BUF_BYTES 16384        // one stage buffer: hi 8 KB + lo 8 KB
#define LO_OFF 8192
#define BATCH_BYTES 2048       // 32 rows x 64 B bf16
#define STG_STRIDE 29
#define STG_WARP 783           // 27 * 29 floats

__device__ __forceinline__ void split2(float x, float y, uint32_t& h, uint32_t& l) {
    asm("cvt.rn.satfinite.bf16x2.f32 %0, %1, %2;" : "=r"(h) : "f"(y), "f"(x));
    float hx = __uint_as_float(h << 16);
    float hy = __uint_as_float(h & 0xffff0000u);
    float lx = x - hx, ly = y - hy;
    asm("cvt.rn.satfinite.bf16x2.f32 %0, %1, %2;" : "=r"(l) : "f"(ly), "f"(lx));
}

__device__ __forceinline__ void ldx4(uint32_t addr, uint32_t* r) {
    asm volatile("ldmatrix.sync.aligned.m8n8.x4.shared.b16 {%0,%1,%2,%3}, [%4];"
                 : "=r"(r[0]), "=r"(r[1]), "=r"(r[2]), "=r"(r[3]) : "r"(addr));
}

__device__ __forceinline__ void mma16816(float* c, const uint32_t* a, const uint32_t* b) {
    asm volatile(
        "mma.sync.aligned.m16n8k16.row.col.f32.bf16.bf16.f32 "
        "{%0,%1,%2,%3}, {%4,%5,%6,%7}, {%8,%9}, {%0,%1,%2,%3};"
        : "+f"(c[0]), "+f"(c[1]), "+f"(c[2]), "+f"(c[3])
        : "r"(a[0]), "r"(a[1]), "r"(a[2]), "r"(a[3]), "r"(b[0]), "r"(b[1]));
}

__global__ __launch_bounds__(THREADS)
void interaction_kernel(const float* __restrict__ dense,
                        const float* __restrict__ sparse,
                        float* __restrict__ out,
                        int B)
{
    __shared__ __align__(1024) char smem[2 * BUF_BYTES];   // 32 KB

    const int tid = threadIdx.x;
    const int wid = tid >> 5;
    const int lane = tid & 31;
    const long bbase = (long)blockIdx.x * GROUP;

    uint32_t sb;
    asm("{ .reg .u64 t; cvta.to.shared.u64 t, %1; cvt.u32.u64 %0, t; }"
        : "=r"(sb) : "l"((void*)smem));

    // ---- load mapping: quarter-warp per feature-row line (coalesced) ----
    const int lr = tid >> 2;           // feature row 0..31
    const int lc = tid & 3;            // 8-float chunk 0..3 within stage
    const int lpos = (lc ^ ((lr >> 1) & 3)) << 4;   // swizzled 16B chunk off
    const uint32_t loff = lr * 64 + lpos;

    // per-batch source pointer for this thread's fixed row lr
    const float* srcg[GROUP];
    bool validg[GROUP];
#pragma unroll
    for (int g = 0; g < GROUP; ++g) {
        const long b = bbase + g;
        validg[g] = (lr < FEAT) && (b < B);
        srcg[g] = (lr == 0)
            ? dense + b * KDIM + lc * 8
            : sparse + ((b * 26) + (lr - 1)) * (long)KDIM + lc * 8;
    }

    // ldmatrix lane selectors (verified rounds 7-9)
    const int arow = lane & 15;
    const int asel = lane >> 4;
    const int brow = (lane & 7) + ((lane & 16) >> 1);
    const int bsel = (lane >> 3) & 1;
    const int aswz = (arow >> 1) & 3;
    const int bswz = (brow >> 1) & 3;

    float acc[6][4] = {};   // T00a,T00b,T01a,T01b,T11a,T11b
    float4 p0[GROUP], p1[GROUP];

    // ---- prologue: prefetch stage 0 ----
#pragma unroll
    for (int g = 0; g < GROUP; ++g) {
        p0[g] = validg[g] ? *reinterpret_cast<const float4*>(srcg[g])
                          : make_float4(0.f, 0.f, 0.f, 0.f);
        p1[g] = validg[g] ? *reinterpret_cast<const float4*>(srcg[g] + 4)
                          : make_float4(0.f, 0.f, 0.f, 0.f);
    }

#pragma unroll
    for (int s2 = 0; s2 < 4; ++s2) {
        char* bufb = smem + (s2 & 1) * BUF_BYTES;

        // ---- split + STS of prefetched stage ----
#pragma unroll
        for (int g = 0; g < GROUP; ++g) {
            uint4 hi, lo;
            split2(p0[g].x, p0[g].y, hi.x, lo.x);
            split2(p0[g].z, p0[g].w, hi.y, lo.y);
            split2(p1[g].x, p1[g].y, hi.z, lo.z);
            split2(p1[g].z, p1[g].w, hi.w, lo.w);
            const uint32_t off = g * BATCH_BYTES + loff;
            *reinterpret_cast<uint4*>(bufb + off) = hi;
            *reinterpret_cast<uint4*>(bufb + LO_OFF + off) = lo;
        }
        __syncthreads();

        // ---- issue prefetch for next stage (hidden under compute) ----
        if (s2 < 3) {
#pragma unroll
            for (int g = 0; g < GROUP; ++g) {
                const float* p = srcg[g] + (s2 + 1) * 32;
                p0[g] = validg[g] ? *reinterpret_cast<const float4*>(p)
                                  : make_float4(0.f, 0.f, 0.f, 0.f);
                p1[g] = validg[g] ? *reinterpret_cast<const float4*>(p + 4)
                                  : make_float4(0.f, 0.f, 0.f, 0.f);
            }
        }

        // ---- compute: 2 k16-steps from buf[s2&1] ----
        const uint32_t hbase = sb + (s2 & 1) * BUF_BYTES + wid * BATCH_BYTES;
        const uint32_t lbase = hbase + LO_OFF;
#pragma unroll
        for (int s = 0; s < 2; ++s) {
            const int ac = 2 * s + asel;
            const int bc = 2 * s + bsel;

            uint32_t A0h[4], A0l[4], A1h[4], A1l[4];
            uint32_t B0h[4], B0l[4], B1h[4], B1l[4];

            const uint32_t offA0 = arow * 64 + ((ac ^ aswz) << 4);
            const uint32_t offA1 = (arow + 16) * 64 + ((ac ^ aswz) << 4);
            const uint32_t offB0 = brow * 64 + ((bc ^ bswz) << 4);
            const uint32_t offB1 = (brow + 16) * 64 + ((bc ^ bswz) << 4);

            ldx4(hbase + offA0, A0h);  ldx4(lbase + offA0, A0l);
            ldx4(hbase + offA1, A1h);  ldx4(lbase + offA1, A1l);
            ldx4(hbase + offB0, B0h);  ldx4(lbase + offB0, B0l);
            ldx4(hbase + offB1, B1h);  ldx4(lbase + offB1, B1l);

            // H * H^T
            mma16816(acc[0], A0h, B0h);      mma16816(acc[1], A0h, B0h + 2);
            mma16816(acc[2], A0h, B1h);      mma16816(acc[3], A0h, B1h + 2);
            mma16816(acc[4], A1h, B1h);      mma16816(acc[5], A1h, B1h + 2);
            // H * L^T
            mma16816(acc[0], A0h, B0l);      mma16816(acc[1], A0h, B0l + 2);
            mma16816(acc[2], A0h, B1l);      mma16816(acc[3], A0h, B1l + 2);
            mma16816(acc[4], A1h, B1l);      mma16816(acc[5], A1h, B1l + 2);
            // L * H^T
            mma16816(acc[0], A0l, B0h);      mma16816(acc[1], A0l, B0h + 2);
            mma16816(acc[2], A0l, B1h);      mma16816(acc[3], A0l, B1h + 2);
            mma16816(acc[4], A1l, B1h);      mma16816(acc[5], A1l, B1h + 2);
        }
        // no trailing barrier: next STS targets the OTHER buffer, whose last
        // readers (compute(s2-1)) all finished before this stage's barrier.
    }

    // ---- Stage per-warp triangle into buf0 (compute(3) reads only buf1) ----
    {
        float* stg = reinterpret_cast<float*>(smem) + wid * STG_WARP;
        const int r0 = lane >> 2;
        const int c0 = (lane & 3) * 2;
        const int MR[6] = {0, 0, 0, 0, 16, 16};
        const int NC[6] = {0, 8, 16, 24, 16, 24};
#pragma unroll
        for (int t = 0; t < 6; ++t) {
#pragma unroll
            for (int hrow = 0; hrow < 2; ++hrow) {
                const int rr = MR[t] + r0 + hrow * 8;
                const int cc = NC[t] + c0;
                if (rr < FEAT && cc < 28) {
                    stg[rr * STG_STRIDE + cc] = acc[t][hrow * 2];
                    if (cc + 1 < 28)
                        stg[rr * STG_STRIDE + cc + 1] = acc[t][hrow * 2 + 1];
                }
            }
        }
    }
    __syncthreads();

    // ---- Coalesced writeout: contiguous 4*351 floats per CTA ----
    const long obase = bbase * NPAIR;
    const long lim = (long)B * NPAIR;
    const float* stg0 = reinterpret_cast<const float*>(smem);
#pragma unroll
    for (int k = 0; k < 11; ++k) {
        const int idx = k * THREADS + tid;
        if (idx < GROUP * NPAIR && obase + idx < lim) {
            const int g = idx / NPAIR;
            const int e = idx - g * NPAIR;
            int i = (int)((53.0f - sqrtf(2809.0f - 8.0f * (float)e)) * 0.5f);
            if (i < 0) i = 0;
            if (i > 25) i = 25;
#pragma unroll
            for (int q = 0; q < 2; ++q) {
                if (i < 25 && e >= (i + 1) * (52 - i) / 2) ++i;
                if (i > 0 && e < i * (53 - i) / 2) --i;
            }
            const int j = i + 1 + (e - i * (53 - i) / 2);
            out[obase + idx] = stg0[g * STG_WARP + i * STG_STRIDE + j];
        }
    }
}

extern "C" void kernel_launch(void* const* d_in, const int* in_sizes, int n_in,
                              void* d_out, int out_size)
{
    const float* dense  = (const float*)d_in[0];   // (B, 128)
    const float* sparse = (const float*)d_in[1];   // (B, 26, 128)
    float* out = (float*)d_out;                    // (B, 351)

    const int B = in_sizes[0] / KDIM;
    const int grid = (B + GROUP - 1) / GROUP;
    interaction_kernel<<<grid, THREADS>>>(dense, sparse, out, B);
}